// round 15
// baseline (speedup 1.0000x reference)
#include <cuda_runtime.h>

#define CRF_B 128
#define CRF_S 1024
#define CRF_T 128
#define CRF_SOS 0
#define CRF_EOS 1
#define NGROUP 2          // independent batches per CTA (one per named-barrier group)
#define GT 128            // threads per group
#define NT (NGROUP * GT)

typedef unsigned long long u64;

__device__ float g_part[CRF_B];
__device__ int   g_count;          // zero-initialized; reset by the reducing thread each run

__device__ __forceinline__ u64 pack2(float lo, float hi) {
    u64 r; asm("mov.b64 %0,{%1,%2};" : "=l"(r) : "f"(lo), "f"(hi)); return r;
}
__device__ __forceinline__ u64 fma2(u64 a, u64 b, u64 c) {
    u64 d; asm("fma.rn.f32x2 %0,%1,%2,%3;" : "=l"(d) : "l"(a), "l"(b), "l"(c)); return d;
}
__device__ __forceinline__ u64 add2(u64 a, u64 b) {
    u64 d; asm("add.rn.f32x2 %0,%1,%2;" : "=l"(d) : "l"(a), "l"(b)); return d;
}
__device__ __forceinline__ void unpack2(u64 v, float& lo, float& hi) {
    asm("mov.b64 {%0,%1},%2;" : "=f"(lo), "=f"(hi) : "l"(v));
}
// Per-group barrier: group g (0/1) uses named barrier g+1 with 128 threads.
// bar.sync has __syncthreads-equivalent memory ordering for participants.
__device__ __forceinline__ void gbar(int g) {
    asm volatile("bar.sync %0, %1;" :: "r"(g + 1), "n"(GT) : "memory");
}

// One CRF step for one group (R4 organization: thread = column, broadcast LDS.128).
// 8 accumulator chains -> fma2 dependency depth 8 (32 cyc) + 3-level add tree.
// APPLY: fold renorm scale published last step (red pre-seeded 1.0 => first is no-op);
//        scale path independent of the dot product -> overlapped by the scheduler.
// PUBLISH: group max of pnew via warp REDUX (p>=0 -> fp32 max == u32 bit max).
template<bool APPLY, bool PUBLISH>
__device__ __forceinline__ void crf_step(
    float (*p_sm)[CRF_T], float* red, const u64* Ereg,
    int& buf, float& pcur, float& Ccum,
    float eexp_t, float m, int j, int lane, int wg, int g)
{
    const ulonglong2* pq = (const ulonglong2*)p_sm[buf];
    u64 a0 = 0, a1 = 0, a2 = 0, a3 = 0, a4 = 0, a5 = 0, a6 = 0, a7 = 0;
#pragma unroll
    for (int k = 0; k < 8; ++k) {            // 32 x LDS.128 (broadcast), 64 x fma2
        ulonglong2 q0 = pq[4 * k + 0];
        ulonglong2 q1 = pq[4 * k + 1];
        ulonglong2 q2 = pq[4 * k + 2];
        ulonglong2 q3 = pq[4 * k + 3];
        a0 = fma2(q0.x, Ereg[8 * k + 0], a0);
        a1 = fma2(q0.y, Ereg[8 * k + 1], a1);
        a2 = fma2(q1.x, Ereg[8 * k + 2], a2);
        a3 = fma2(q1.y, Ereg[8 * k + 3], a3);
        a4 = fma2(q2.x, Ereg[8 * k + 4], a4);
        a5 = fma2(q2.y, Ereg[8 * k + 5], a5);
        a6 = fma2(q3.x, Ereg[8 * k + 6], a6);
        a7 = fma2(q3.y, Ereg[8 * k + 7], a7);
    }

    float ee = eexp_t;          // pre-scaled in APPLY steps
    float pc = pcur;
    if (APPLY) {                // alpha = log(p) + Ccum preserved exactly
        float M = fmaxf(fmaxf(red[0], red[1]), fmaxf(red[2], red[3]));
        float inv = 1.0f / M;
        Ccum += __logf(M);
        ee = inv * eexp_t;
        pc = inv * pcur;
    }

    u64 s2 = add2(add2(add2(a0, a1), add2(a2, a3)),
                  add2(add2(a4, a5), add2(a6, a7)));
    float slo, shi;
    unpack2(s2, slo, shi);
    float ssum = slo + shi;

    float v    = ssum * ee;
    float pnew = (m > 0.5f) ? v : pc;        // masked step keeps alphas unchanged

    if (PUBLISH) {
        unsigned mx = __reduce_max_sync(0xffffffffu, __float_as_uint(pnew));
        if (lane == 0) red[wg] = __uint_as_float(mx);
    }

    buf ^= 1;
    p_sm[buf][j] = pnew;
    pcur = pnew;
    gbar(g);                                  // per-group barrier only
}

__global__ void __launch_bounds__(NT, 1) crf_kernel(
    const float* __restrict__ em, const float* __restrict__ trans,
    const float* __restrict__ mask, const int* __restrict__ tags,
    float* __restrict__ out)
{
    __shared__ __align__(16) float p_sm[NGROUP][2][CRF_T];
    __shared__ float msk_sm[NGROUP][CRF_S];
    __shared__ float red_sm[NGROUP][4];
    __shared__ float red2_sm[NGROUP][8];

    const int tid  = threadIdx.x;
    const int g    = tid >> 7;               // group 0/1 = independent batch
    const int j    = tid & (GT - 1);         // column owned by this thread
    const int lane = tid & 31;
    const int wg   = (tid >> 5) & 3;         // warp index within group
    const int b    = blockIdx.x * NGROUP + g;
    const float* emb = em + (size_t)b * CRF_S * CRF_T;

    float (*p)[CRF_T] = p_sm[g];
    float* red  = red_sm[g];
    float* red2 = red2_sm[g];
    float* msk  = msk_sm[g];

    // ---- E column (exp of transition column j) in registers: 64 packed f32x2 ----
    u64 Ereg[CRF_T / 2];
#pragma unroll
    for (int k = 0; k < CRF_T / 2; ++k) {
        float a = __expf(trans[(2 * k) * CRF_T + j]);
        float c = __expf(trans[(2 * k + 1) * CRF_T + j]);
        Ereg[k] = pack2(a, c);
    }

    for (int s = j; s < CRF_S; s += GT) msk[s] = mask[b * CRF_S + s];
    if (j < 4) red[j] = 1.0f;                // identity renorm for the first apply

    // ---- alpha_0 in exp domain ----
    float pcur = __expf(trans[CRF_SOS * CRF_T + j] + emb[j]);
    p[0][j] = pcur;

    // ---- emission register pipeline: eexp ready rows 1..4, raw in flight 5..8 ----
    float eexp[4], eraw[4];
#pragma unroll
    for (int u = 0; u < 4; ++u) eexp[u] = __expf(emb[(1 + u) * CRF_T + j]);
#pragma unroll
    for (int u = 0; u < 4; ++u) eraw[u] = emb[(5 + u) * CRF_T + j];

    float Ccum = 0.0f;
    int buf = 0;
    gbar(g);

    // ---- main scan: 255 blocks of 4 steps cover t = 1..1020 ----
    for (int blk = 0; blk < (CRF_S - 4) / 4; ++blk) {
        const int t0 = 1 + blk * 4;

        float m0 = msk[t0 + 0], m1 = msk[t0 + 1];
        float m2 = msk[t0 + 2], m3 = msk[t0 + 3];

        float enew[4];
#pragma unroll
        for (int u = 0; u < 4; ++u) enew[u] = eraw[u];     // rows t0+4..t0+7 (arrived)
#pragma unroll
        for (int u = 0; u < 4; ++u) {                      // issue rows t0+8..t0+11
            int r = t0 + 8 + u;
            eraw[u] = (r < CRF_S) ? emb[r * CRF_T + j] : 0.0f;
        }

        crf_step<true,  false>(p, red, Ereg, buf, pcur, Ccum, eexp[0], m0, j, lane, wg, g);
        crf_step<false, false>(p, red, Ereg, buf, pcur, Ccum, eexp[1], m1, j, lane, wg, g);
        crf_step<false, false>(p, red, Ereg, buf, pcur, Ccum, eexp[2], m2, j, lane, wg, g);
        crf_step<false, true >(p, red, Ereg, buf, pcur, Ccum, eexp[3], m3, j, lane, wg, g);

#pragma unroll
        for (int u = 0; u < 4; ++u) eexp[u] = __expf(enew[u]);   // off-chain convert
    }

    // ---- epilogue: t = 1021..1023 ----
    crf_step<true,  false>(p, red, Ereg, buf, pcur, Ccum, eexp[0], msk[CRF_S - 3], j, lane, wg, g);
    crf_step<false, false>(p, red, Ereg, buf, pcur, Ccum, eexp[1], msk[CRF_S - 2], j, lane, wg, g);
    crf_step<false, false>(p, red, Ereg, buf, pcur, Ccum, eexp[2], msk[CRF_S - 1], j, lane, wg, g);

    // ---- partition = Ccum + log( sum_j p_j * exp(T[j, EOS]) ) ----
    float vterm = pcur * __expf(trans[j * CRF_T + CRF_EOS]);
#pragma unroll
    for (int off = 16; off; off >>= 1)
        vterm += __shfl_xor_sync(0xffffffffu, vterm, off);
    if (lane == 0) red[wg] = vterm;
    gbar(g);
    float Z = red[0] + red[1] + red[2] + red[3];
    float partition = Ccum + __logf(Z);
    gbar(g);

    // ---- gold-path score ----
    const int* tg = tags + b * CRF_S;
    float sc  = 0.0f;
    float nvf = 0.0f;
    for (int s = j; s < CRF_S; s += GT) {
        nvf += msk[s];
        if (s == 0) {
            int t0g = tg[0];
            sc += trans[CRF_SOS * CRF_T + t0g] + emb[t0g];
        } else {
            int tc = tg[s], tp = tg[s - 1];
            sc += msk[s] * (emb[s * CRF_T + tc] + trans[tp * CRF_T + tc]);
        }
    }
#pragma unroll
    for (int off = 16; off; off >>= 1) {
        sc  += __shfl_xor_sync(0xffffffffu, sc, off);
        nvf += __shfl_xor_sync(0xffffffffu, nvf, off);
    }
    if (lane == 0) { red2[wg] = sc; red2[4 + wg] = nvf; }
    gbar(g);
    float SC = red2[0] + red2[1] + red2[2] + red2[3];
    float NV = red2[4] + red2[5] + red2[6] + red2[7];
    int last = (int)(NV + 0.5f) - 1;
    SC += trans[tg[last] * CRF_T + CRF_EOS];

    // ---- last-done final reduction (deterministic fixed-order sum) ----
    if (j == 0) {
        g_part[b] = partition - SC;
        __threadfence();
        if (atomicAdd(&g_count, 1) == CRF_B - 1) {
            __threadfence();
            float s = 0.0f;
#pragma unroll 8
            for (int k = 0; k < CRF_B; ++k) s += g_part[k];
            out[0] = s;
            g_count = 0;            // reset for the next graph replay
            __threadfence();
        }
    }
}

extern "C" void kernel_launch(void* const* d_in, const int* in_sizes, int n_in,
                              void* d_out, int out_size) {
    const float* em = (const float*)d_in[0];   // emissions (B,S,T) f32
    const float* tr = (const float*)d_in[1];   // transition (T,T)  f32
    const float* mk = (const float*)d_in[2];   // mask (B,S)        f32
    const int*   tg = (const int*)d_in[3];     // tags (B,S)        i32

    crf_kernel<<<CRF_B / NGROUP, NT>>>(em, tr, mk, tg, (float*)d_out);
}